// round 13
// baseline (speedup 1.0000x reference)
#include <cuda_runtime.h>
#include <math.h>

// ---------------------------------------------------------------------------
// Problem constants: B=4, N=16384 (H=W=128), C=128, HEADS=2, dh=64, SR=4
// ---------------------------------------------------------------------------
#define BATCH   4
#define NQ      16384
#define C_DIM   128
#define HEADS   2
#define DH      64
#define NKV     1024
#define QTILE   128
#define KCH     32
#define KCONV   2048
#define MCONV   (BATCH * NKV)     // 4096
#define MQ      (BATCH * NQ)      // 65536

// Scratch (allocation-free rule: __device__ globals)
__device__ float g_xrp  [MCONV * C_DIM];          // xr, fragment-permuted [kcg][m][16]
__device__ float g_kp   [BATCH * HEADS * 4 * NKV * 16];   // K frag-permuted [bh][kg_d][key][pos16]
__device__ float g_vp   [BATCH * HEADS * 64 * DH * 16];   // V^T frag-permuted [bh][kg_key][d][pos16]
__device__ float g_aop  [MQ * C_DIM];             // attn out, fragment-permuted
__device__ float g_cpart[4 * MCONV * C_DIM];      // conv split-K partials
// Pre-permuted tf32 weights: [kcg][n][pos16], k = kcg*16 + perm16(pos)
__device__ float g_wtq[C_DIM * C_DIM];
__device__ float g_wtk[C_DIM * C_DIM];
__device__ float g_wtv[C_DIM * C_DIM];
__device__ float g_wtp[C_DIM * C_DIM];
__device__ float g_wct[C_DIM * KCONV];

// ---------------------------------------------------------------------------
// tf32 helpers (fragment mappings validated R5-R12)
// ---------------------------------------------------------------------------
__device__ __forceinline__ unsigned f2tf(float x) {
    unsigned r;
    asm("cvt.rna.tf32.f32 %0, %1;" : "=r"(r) : "f"(x));
    return r;
}
__device__ __forceinline__ float f2tff(float x) {
    return __uint_as_float(f2tf(x));
}
__device__ __forceinline__ void mma_tf32(float& d0, float& d1, float& d2, float& d3,
                                         unsigned a0, unsigned a1, unsigned a2, unsigned a3,
                                         unsigned b0, unsigned b1) {
    asm volatile(
        "mma.sync.aligned.m16n8k8.row.col.f32.tf32.tf32.f32 "
        "{%0,%1,%2,%3},{%4,%5,%6,%7},{%8,%9},{%0,%1,%2,%3};"
        : "+f"(d0), "+f"(d1), "+f"(d2), "+f"(d3)
        : "r"(a0), "r"(a1), "r"(a2), "r"(a3), "r"(b0), "r"(b1));
}

// 4x4 transpose within a 16-group (involution): kk at pos (kk&3)*4 + (kk>>2).
__device__ __forceinline__ int perm16(int p) { return (p & 3) * 4 + (p >> 2); }

// Permuted scatter-store for activations into smem: chunk layout [kg][row][pos16].
__device__ __forceinline__ void sts_perm(float* s, int rows16, int row, int c4, float4 v) {
    float* base = s + ((c4 >> 2) * rows16 * 16) + row * 16 + (c4 & 3);
    base[0] = v.x; base[4] = v.y; base[8] = v.z; base[12] = v.w;
}

// ---------------------------------------------------------------------------
// Weight pack kernels
// ---------------------------------------------------------------------------
__global__ void pack_w4_kernel(const float* __restrict__ s0, const float* __restrict__ s1,
                               const float* __restrict__ s2, const float* __restrict__ s3,
                               float* __restrict__ d0, float* __restrict__ d1,
                               float* __restrict__ d2, float* __restrict__ d3) {
    int id = blockIdx.x * 256 + threadIdx.x;
    int mat = id >> 14, e = id & 16383;
    const float* s = (mat == 0) ? s0 : (mat == 1) ? s1 : (mat == 2) ? s2 : s3;
    float*       d = (mat == 0) ? d0 : (mat == 1) ? d1 : (mat == 2) ? d2 : d3;
    int pos = e & 15, n = (e >> 4) & 127, kcg = e >> 11;
    int k = kcg * 16 + perm16(pos);
    d[e] = f2tff(s[k * 128 + n]);
}

__global__ void pack_wconv_kernel(const float* __restrict__ src, float* __restrict__ dst) {
    int e = blockIdx.x * 256 + threadIdx.x;
    int pos = e & 15, n = (e >> 4) & 127, kcg = e >> 11;
    int k = kcg * 16 + perm16(pos);
    dst[e] = f2tff(src[(size_t)k * 128 + n]);
}

// ---------------------------------------------------------------------------
// Smem-free warp-autonomous GEMM core (R12-validated).
// Aperm: [kcg=8][M][16] fragment-ready. 8 warps: mg=w&3 (16 rows), ng=w>>2.
// ---------------------------------------------------------------------------
__device__ __forceinline__ void gemm_frag_compute(const float* __restrict__ Ap,
                                                  const float* __restrict__ Wp,
                                                  size_t M, size_t m,
                                                  int ng, int gid, int tig,
                                                  float oacc[8][4]) {
#pragma unroll
    for (int kcg = 0; kcg < 8; kcg++) {
        const float* ab = Ap + ((size_t)kcg * M + m) * 16 + (tig << 2);
        float4 alo = *(const float4*)ab;
        float4 ahi = *(const float4*)(ab + 128);
        unsigned a0 = __float_as_uint(alo.x), a1 = __float_as_uint(ahi.x);
        unsigned a2 = __float_as_uint(alo.y), a3 = __float_as_uint(ahi.y);
        unsigned c0 = __float_as_uint(alo.z), c1 = __float_as_uint(ahi.z);
        unsigned c2 = __float_as_uint(alo.w), c3 = __float_as_uint(ahi.w);
        const float* wb = Wp + ((size_t)kcg * 128 + ng * 64 + gid) * 16 + (tig << 2);
#pragma unroll
        for (int nt = 0; nt < 8; nt++) {
            float4 bv = *(const float4*)(wb + nt * 128);
            mma_tf32(oacc[nt][0], oacc[nt][1], oacc[nt][2], oacc[nt][3],
                     a0, a1, a2, a3, __float_as_uint(bv.x), __float_as_uint(bv.y));
            mma_tf32(oacc[nt][0], oacc[nt][1], oacc[nt][2], oacc[nt][3],
                     c0, c1, c2, c3, __float_as_uint(bv.z), __float_as_uint(bv.w));
        }
    }
}

__global__ __launch_bounds__(256)
void gemm_frag_kernel(const float* __restrict__ Ap, const float* __restrict__ Wp,
                      float* __restrict__ out) {
    int tid = threadIdx.x;
    int w = tid >> 5, lane = tid & 31;
    int gid = lane >> 2, tig = lane & 3;
    int mg = w & 3, ng = w >> 2;
    size_t m = ((size_t)blockIdx.x << 6) + mg * 16 + gid;
    float oacc[8][4];
#pragma unroll
    for (int i = 0; i < 8; i++)
#pragma unroll
        for (int j = 0; j < 4; j++) oacc[i][j] = 0.f;
    gemm_frag_compute(Ap, Wp, (size_t)MQ, m, ng, gid, tig, oacc);
    size_t r0 = m * 128, r1 = r0 + 8 * 128;
#pragma unroll
    for (int nt = 0; nt < 8; nt++) {
        int c = ng * 64 + nt * 8 + 2 * tig;
        *(float2*)&out[r0 + c] = make_float2(oacc[nt][0], oacc[nt][1]);
        *(float2*)&out[r1 + c] = make_float2(oacc[nt][2], oacc[nt][3]);
    }
}

// ---------------------------------------------------------------------------
// K/V projection with fragment-permuted epilogues (N-half ng == head h).
//   K: kp[((bh)*4 + d_loc>>4)*1024 + key]*16 + perm16(d_loc&15)
//   V: vp[((bh)*64 + key>>4)*64 + d_loc]*16 + perm16(key&15)
// blockIdx.y: 0 = K, 1 = V. m = b*1024 + key.
// ---------------------------------------------------------------------------
__global__ __launch_bounds__(256)
void kv_proj_kernel(const float* __restrict__ Ap,
                    const float* __restrict__ Wpk, const float* __restrict__ Wpv,
                    float* __restrict__ kp, float* __restrict__ vp) {
    int tid = threadIdx.x;
    int w = tid >> 5, lane = tid & 31;
    int gid = lane >> 2, tig = lane & 3;
    int mg = w & 3, ng = w >> 2;        // ng == head
    int isV = blockIdx.y;
    size_t m = ((size_t)blockIdx.x << 6) + mg * 16 + gid;
    float oacc[8][4];
#pragma unroll
    for (int i = 0; i < 8; i++)
#pragma unroll
        for (int j = 0; j < 4; j++) oacc[i][j] = 0.f;
    gemm_frag_compute(Ap, isV ? Wpv : Wpk, (size_t)MCONV, m, ng, gid, tig, oacc);

    int b   = (int)(m >> 10);
    int key = (int)(m & 1023);          // rows key, key+8
    int bh  = b * HEADS + ng;
    if (!isV) {
#pragma unroll
        for (int nt = 0; nt < 8; nt++) {
            int dl = nt * 8 + 2 * tig;          // d_local, even
            int kg = dl >> 4;
            int p0 = perm16(dl & 15);           // p(dl+1) = p0+4
            float* b0 = kp + (((size_t)bh * 4 + kg) * NKV + key) * 16;
            float* b1 = b0 + 8 * 16;
            b0[p0]     = f2tff(oacc[nt][0]);
            b0[p0 + 4] = f2tff(oacc[nt][1]);
            b1[p0]     = f2tff(oacc[nt][2]);
            b1[p0 + 4] = f2tff(oacc[nt][3]);
        }
    } else {
        int kgk = key >> 4;                     // same for key and key+8
        int pa = perm16(gid), pb = perm16(gid + 8);
#pragma unroll
        for (int nt = 0; nt < 8; nt++) {
            int dl = nt * 8 + 2 * tig;
            float* bse = vp + (((size_t)bh * 64 + kgk) * DH + dl) * 16;
            bse[pa]      = f2tff(oacc[nt][0]);
            bse[16 + pa] = f2tff(oacc[nt][1]);   // d+1
            bse[pb]      = f2tff(oacc[nt][2]);
            bse[16 + pb] = f2tff(oacc[nt][3]);
        }
    }
}

// ---------------------------------------------------------------------------
// Conv split-K x4 (R10-validated, unchanged).
// ---------------------------------------------------------------------------
__global__ __launch_bounds__(256)
void conv_part_kernel(const float* __restrict__ x, const float* __restrict__ Wp,
                      float* __restrict__ cpart) {
    __shared__ float sA[2][1024];
    int m0 = blockIdx.x << 5;
    int kz = blockIdx.y;
    int tid = threadIdx.x;
    int w = tid >> 5, lane = tid & 31;
    int gid = lane >> 2, tig = lane & 3;
    int rg = w & 1, cg = w >> 1;

    int lrow = tid >> 3, lc4 = tid & 7;
    int am = m0 + lrow;
    int ab = am >> 10, apos = am & 1023, aoh = apos >> 5, aow = apos & 31;
    const float* abase = x + ((size_t)((ab * 128 + (aoh << 2) + kz) * 128 + (aow << 2))) * 128;

    float oacc[4][4];
#pragma unroll
    for (int i = 0; i < 4; i++)
#pragma unroll
        for (int j = 0; j < 4; j++) oacc[i][j] = 0.f;

    float4 av = *(const float4*)(abase + (lc4 << 2));
    {
        float4 a = av;
        a.x = f2tff(a.x); a.y = f2tff(a.y); a.z = f2tff(a.z); a.w = f2tff(a.w);
        sts_perm(sA[0], 32, lrow, lc4, a);
    }
    __syncthreads();

#pragma unroll 1
    for (int cc = 0; cc < 16; cc++) {
        int cur = cc & 1;
        if (cc < 15) {
            int nc = cc + 1;
            int kw = nc >> 2, ci0 = (nc & 3) << 5;
            av = *(const float4*)(abase + (size_t)kw * 128 + ci0 + (lc4 << 2));
        }
        int kcg0 = (kz * 16 + cc) * 2;
#pragma unroll
        for (int kg = 0; kg < 2; kg++) {
            const float* pa = &sA[cur][kg * 512 + (rg * 16 + gid) * 16 + (tig << 2)];
            float4 alo = *(const float4*)pa;
            float4 ahi = *(const float4*)(pa + 128);
            unsigned a0 = __float_as_uint(alo.x), a1 = __float_as_uint(ahi.x);
            unsigned a2 = __float_as_uint(alo.y), a3 = __float_as_uint(ahi.y);
            unsigned c0 = __float_as_uint(alo.z), c1 = __float_as_uint(ahi.z);
            unsigned c2 = __float_as_uint(alo.w), c3 = __float_as_uint(ahi.w);
            const float* wb = Wp + ((size_t)(kcg0 + kg) * 128 + cg * 32 + gid) * 16 + (tig << 2);
#pragma unroll
            for (int nt = 0; nt < 4; nt++) {
                float4 bv = *(const float4*)(wb + nt * 128);
                mma_tf32(oacc[nt][0], oacc[nt][1], oacc[nt][2], oacc[nt][3],
                         a0, a1, a2, a3, __float_as_uint(bv.x), __float_as_uint(bv.y));
                mma_tf32(oacc[nt][0], oacc[nt][1], oacc[nt][2], oacc[nt][3],
                         c0, c1, c2, c3, __float_as_uint(bv.z), __float_as_uint(bv.w));
            }
        }
        if (cc < 15) {
            float4 a = av;
            a.x = f2tff(a.x); a.y = f2tff(a.y); a.z = f2tff(a.z); a.w = f2tff(a.w);
            sts_perm(sA[1 - cur], 32, lrow, lc4, a);
            __syncthreads();
        }
    }

    float* pb = cpart + (size_t)kz * MCONV * 128;
    size_t r0 = (size_t)(m0 + rg * 16 + gid) * 128;
    size_t r1 = r0 + 8 * 128;
#pragma unroll
    for (int nt = 0; nt < 4; nt++) {
        int c = cg * 32 + nt * 8 + 2 * tig;
        *(float2*)&pb[r0 + c] = make_float2(oacc[nt][0], oacc[nt][1]);
        *(float2*)&pb[r1 + c] = make_float2(oacc[nt][2], oacc[nt][3]);
    }
}

// ---------------------------------------------------------------------------
// LN combine -> permuted xr (R12-validated).
// ---------------------------------------------------------------------------
__global__ __launch_bounds__(128)
void ln_combine_kernel(const float* __restrict__ cpart, const float* __restrict__ bias,
                       const float* __restrict__ gamma, const float* __restrict__ beta,
                       float* __restrict__ xrp) {
    __shared__ float ss[4], ssq[4], sMR[2];
    int m = blockIdx.x, c = threadIdx.x;
    int wd = c >> 5, ln = c & 31;
    float v = bias[c];
#pragma unroll
    for (int z = 0; z < 4; z++)
        v += cpart[((size_t)z * MCONV + m) * 128 + c];
    float s = v, sq = v * v;
#pragma unroll
    for (int off = 16; off > 0; off >>= 1) {
        s  += __shfl_xor_sync(0xffffffffu, s, off);
        sq += __shfl_xor_sync(0xffffffffu, sq, off);
    }
    if (ln == 0) { ss[wd] = s; ssq[wd] = sq; }
    __syncthreads();
    if (c == 0) {
        float S = ss[0] + ss[1] + ss[2] + ss[3];
        float Q = ssq[0] + ssq[1] + ssq[2] + ssq[3];
        float mu = S * 0.0078125f;
        float var = Q * 0.0078125f - mu * mu;
        sMR[0] = mu; sMR[1] = rsqrtf(var + 1e-6f);
    }
    __syncthreads();
    float r = (v - sMR[0]) * sMR[1] * gamma[c] + beta[c];
    int kcg = c >> 4, pp = perm16(c & 15);
    xrp[((size_t)kcg * MCONV + m) * 16 + pp] = f2tff(r);
}

// ---------------------------------------------------------------------------
// Fused Qproj + flash attention, K/V fragments DIRECT FROM GLOBAL.
// No K/V smem staging, no mainloop barriers. sP warp-private (stride 36).
// ---------------------------------------------------------------------------
__global__ __launch_bounds__(256)
void attn_fused_kernel(const float* __restrict__ x, const float* __restrict__ Wqp,
                       const float* __restrict__ Kp, const float* __restrict__ Vp,
                       float* __restrict__ AOP) {
    __shared__ float smemU[9088];
    float* sP  = smemU + 4480;     // 128*36 (mainloop)
    float* sSt = smemU;            // prologue staging: 2 x 4096
    float* sQ  = smemU;            // prologue Q park: 128*68

    int b  = blockIdx.z, h = blockIdx.y;
    int n0 = blockIdx.x * QTILE;
    int tid  = threadIdx.x;
    int w    = tid >> 5;
    int lane = tid & 31;
    int gid  = lane >> 2;
    int tig  = lane & 3;

    // ===== PROLOGUE: Q = x_tile @ Wq[:, h*64 .. h*64+63]  (R11-validated) =====
    {
        const float* A = x + ((size_t)(b * NQ + n0)) * C_DIM;
        int lrow = tid >> 3, lc4 = tid & 7;
        float qc[8][4];
#pragma unroll
        for (int i = 0; i < 8; i++)
#pragma unroll
            for (int j = 0; j < 4; j++) qc[i][j] = 0.f;

        float4 av[4];
#pragma unroll
        for (int i = 0; i < 4; i++)
            av[i] = *(const float4*)&A[(size_t)(lrow + (i << 5)) * 128 + (lc4 << 2)];
#pragma unroll
        for (int i = 0; i < 4; i++) {
            float4 a = av[i];
            a.x = f2tff(a.x); a.y = f2tff(a.y); a.z = f2tff(a.z); a.w = f2tff(a.w);
            sts_perm(sSt, 128, lrow + (i << 5), lc4, a);
        }
        __syncthreads();

#pragma unroll
        for (int kc = 0; kc < 4; kc++) {
            int cur = kc & 1;
            if (kc < 3) {
#pragma unroll
                for (int i = 0; i < 4; i++)
                    av[i] = *(const float4*)&A[(size_t)(lrow + (i << 5)) * 128 + ((kc + 1) << 5) + (lc4 << 2)];
            }
#pragma unroll
            for (int kg = 0; kg < 2; kg++) {
                const float* pa = &sSt[cur * 4096 + kg * 2048 + (w * 16 + gid) * 16 + (tig << 2)];
                float4 alo = *(const float4*)pa;
                float4 ahi = *(const float4*)(pa + 128);
                unsigned a0 = __float_as_uint(alo.x), a1 = __float_as_uint(ahi.x);
                unsigned a2 = __float_as_uint(alo.y), a3 = __float_as_uint(ahi.y);
                unsigned c0 = __float_as_uint(alo.z), c1 = __float_as_uint(ahi.z);
                unsigned c2 = __float_as_uint(alo.w), c3 = __float_as_uint(ahi.w);
                const float* wb = Wqp + ((size_t)(kc * 2 + kg) * 128 + h * 64 + gid) * 16 + (tig << 2);
#pragma unroll
                for (int nt = 0; nt < 8; nt++) {
                    float4 bv = *(const float4*)(wb + nt * 128);
                    mma_tf32(qc[nt][0], qc[nt][1], qc[nt][2], qc[nt][3],
                             a0, a1, a2, a3, __float_as_uint(bv.x), __float_as_uint(bv.y));
                    mma_tf32(qc[nt][0], qc[nt][1], qc[nt][2], qc[nt][3],
                             c0, c1, c2, c3, __float_as_uint(bv.z), __float_as_uint(bv.w));
                }
            }
            if (kc < 3) {
#pragma unroll
                for (int i = 0; i < 4; i++) {
                    float4 a = av[i];
                    a.x = f2tff(a.x); a.y = f2tff(a.y); a.z = f2tff(a.z); a.w = f2tff(a.w);
                    sts_perm(sSt + (1 - cur) * 4096, 128, lrow + (i << 5), lc4, a);
                }
                __syncthreads();
            }
        }
        __syncthreads();

        int r0 = w * 16 + gid, r1 = r0 + 8;
#pragma unroll
        for (int nt = 0; nt < 8; nt++) {
            int c = nt * 8 + 2 * tig;
            float2 e0, e1;
            e0.x = f2tff(qc[nt][0] * 0.125f); e0.y = f2tff(qc[nt][1] * 0.125f);
            e1.x = f2tff(qc[nt][2] * 0.125f); e1.y = f2tff(qc[nt][3] * 0.125f);
            *(float2*)&sQ[r0 * 68 + c] = e0;
            *(float2*)&sQ[r1 * 68 + c] = e1;
        }
        __syncthreads();
    }

    unsigned qa[8][4];
    {
        int r0 = w * 16 + gid, r1 = r0 + 8;
#pragma unroll
        for (int ks = 0; ks < 8; ks++) {
            int c = ks * 8 + tig;
            qa[ks][0] = __float_as_uint(sQ[r0 * 68 + c]);
            qa[ks][1] = __float_as_uint(sQ[r1 * 68 + c]);
            qa[ks][2] = __float_as_uint(sQ[r0 * 68 + c + 4]);
            qa[ks][3] = __float_as_uint(sQ[r1 * 68 + c + 4]);
        }
    }
    __syncthreads();   // all warps done reading sQ before sP (aliased) is written

    // ===== MAINLOOP: K/V fragments direct from global, barrier-free =====
    int bh = b * HEADS + h;
    const float* kpt = Kp + (size_t)bh * 4 * NKV * 16 + gid * 16 + (tig << 2);
    const float* vpt = Vp + (size_t)bh * 64 * DH * 16 + gid * 16 + (tig << 2);

    float oacc[8][4];
#pragma unroll
    for (int i = 0; i < 8; i++)
#pragma unroll
        for (int j = 0; j < 4; j++) oacc[i][j] = 0.f;
    float m0r = -1e30f, m1r = -1e30f, l0 = 0.f, l1 = 0.f;
    int r0off = (w * 16 + gid) * 36;
    int r1off = r0off + 8 * 36;

#pragma unroll 1
    for (int kc = 0; kc < NKV / KCH; kc++) {
        // ---- QK: S[16x32] per warp; B-frags = LDG.128 from Kp ----
        float sacc[4][4];
#pragma unroll
        for (int i = 0; i < 4; i++)
#pragma unroll
            for (int j = 0; j < 4; j++) sacc[i][j] = 0.f;
#pragma unroll
        for (int kg = 0; kg < 4; kg++) {
            float4 bv[4];
#pragma unroll
            for (int nt = 0; nt < 4; nt++)
                bv[nt] = *(const float4*)(kpt + (size_t)(kg * NKV + kc * KCH + nt * 8) * 16);
#pragma unroll
            for (int nt = 0; nt < 4; nt++) {
                mma_tf32(sacc[nt][0], sacc[nt][1], sacc[nt][2], sacc[nt][3],
                         qa[2 * kg][0], qa[2 * kg][1], qa[2 * kg][2], qa[2 * kg][3],
                         __float_as_uint(bv[nt].x), __float_as_uint(bv[nt].y));
                mma_tf32(sacc[nt][0], sacc[nt][1], sacc[nt][2], sacc[nt][3],
                         qa[2 * kg + 1][0], qa[2 * kg + 1][1], qa[2 * kg + 1][2], qa[2 * kg + 1][3],
                         __float_as_uint(bv[nt].z), __float_as_uint(bv[nt].w));
            }
        }

        // ---- online softmax (unchanged) ----
        float cm0 = -1e30f, cm1 = -1e30f;
#pragma unroll
        for (int nt = 0; nt < 4; nt++) {
            cm0 = fmaxf(cm0, fmaxf(sacc[nt][0], sacc[nt][1]));
            cm1 = fmaxf(cm1, fmaxf(sacc[nt][2], sacc[nt][3]));
        }
        cm0 = fmaxf(cm0, __shfl_xor_sync(0xffffffffu, cm0, 1));
        cm0 = fmaxf(cm0, __shfl_xor_sync(0xffffffffu, cm0, 2));
        cm1 = fmaxf(cm1, __shfl_xor_sync(0xffffffffu, cm1, 1));
        cm1 = fmaxf(cm1, __shfl_xor_sync(0xffffffffu, cm1, 2));
        float mn0 = fmaxf(m0r, cm0), mn1 = fmaxf(m1r, cm1);
        float al0 = __expf(m0r - mn0), al1 = __expf(m1r - mn1);
        float ps0 = 0.f, ps1 = 0.f;
#pragma unroll
        for (int nt = 0; nt < 4; nt++) {
            float p0 = __expf(sacc[nt][0] - mn0);
            float p1 = __expf(sacc[nt][1] - mn0);
            float p2 = __expf(sacc[nt][2] - mn1);
            float p3 = __expf(sacc[nt][3] - mn1);
            ps0 += p0 + p1;
            ps1 += p2 + p3;
            int co = nt * 8 + 2 * tig;
            float2 e0, e1;
            e0.x = f2tff(p0); e0.y = f2tff(p1);
            e1.x = f2tff(p2); e1.y = f2tff(p3);
            *(float2*)&sP[r0off + co] = e0;
            *(float2*)&sP[r1off + co] = e1;
        }
        ps0 += __shfl_xor_sync(0xffffffffu, ps0, 1);
        ps0 += __shfl_xor_sync(0xffffffffu, ps0, 2);
        ps1 += __shfl_xor_sync(0xffffffffu, ps1, 1);
        ps1 += __shfl_xor_sync(0xffffffffu, ps1, 2);
        l0 = l0 * al0 + ps0;  m0r = mn0;
        l1 = l1 * al1 + ps1;  m1r = mn1;
#pragma unroll
        for (int nt = 0; nt < 8; nt++) {
            oacc[nt][0] *= al0; oacc[nt][1] *= al0;
            oacc[nt][2] *= al1; oacc[nt][3] *= al1;
        }
        __syncwarp();

        // ---- PV: O[16x64] += P[16x32] * V[32x64]; B-frags = LDG.128 from Vp ----
#pragma unroll
        for (int kgk = 0; kgk < 2; kgk++) {
            int ks0 = 2 * kgk, ks1 = ks0 + 1;
            unsigned a0 = __float_as_uint(sP[r0off + ks0 * 8 + tig]);
            unsigned a1 = __float_as_uint(sP[r1off + ks0 * 8 + tig]);
            unsigned a2 = __float_as_uint(sP[r0off + ks0 * 8 + tig + 4]);
            unsigned a3 = __float_as_uint(sP[r1off + ks0 * 8 + tig + 4]);
            unsigned d0 = __float_as_uint(sP[r0off + ks1 * 8 + tig]);
            unsigned d1 = __float_as_uint(sP[r1off + ks1 * 8 + tig]);
            unsigned d2 = __float_as_uint(sP[r0off + ks1 * 8 + tig + 4]);
            unsigned d3 = __float_as_uint(sP[r1off + ks1 * 8 + tig + 4]);
            const float* vb = vpt + (size_t)(kc * 2 + kgk) * DH * 16;
#pragma unroll
            for (int nt = 0; nt < 8; nt++) {
                float4 bv = *(const float4*)(vb + (size_t)(nt * 8) * 16);
                mma_tf32(oacc[nt][0], oacc[nt][1], oacc[nt][2], oacc[nt][3],
                         a0, a1, a2, a3, __float_as_uint(bv.x), __float_as_uint(bv.y));
                mma_tf32(oacc[nt][0], oacc[nt][1], oacc[nt][2], oacc[nt][3],
                         d0, d1, d2, d3, __float_as_uint(bv.z), __float_as_uint(bv.w));
            }
        }
    }

    // ===== EPILOGUE: permuted fragment-ready ao (R12-validated) =====
    float inv0 = 1.f / l0, inv1 = 1.f / l1;
    size_t mrow = (size_t)(b * NQ + n0 + w * 16 + gid);
#pragma unroll
    for (int nt = 0; nt < 8; nt++) {
        int c = h * 64 + nt * 8 + 2 * tig;
        int kcg = c >> 4;
        int pp = perm16(c & 15);
        float* base0 = AOP + ((size_t)kcg * MQ + mrow) * 16;
        float* base1 = base0 + 128;
        base0[pp]     = f2tff(oacc[nt][0] * inv0);
        base0[pp + 4] = f2tff(oacc[nt][1] * inv0);
        base1[pp]     = f2tff(oacc[nt][2] * inv1);
        base1[pp + 4] = f2tff(oacc[nt][3] * inv1);
    }
}

// ---------------------------------------------------------------------------
// Launch. Inputs: x, Wq, Wk, Wv, Wproj, sr_kernel, sr_bias, gamma, beta.
// ---------------------------------------------------------------------------
extern "C" void kernel_launch(void* const* d_in, const int* in_sizes, int n_in,
                              void* d_out, int out_size) {
    const float* x     = (const float*)d_in[0];
    const float* Wq    = (const float*)d_in[1];
    const float* Wk    = (const float*)d_in[2];
    const float* Wv    = (const float*)d_in[3];
    const float* Wp    = (const float*)d_in[4];
    const float* Wsr   = (const float*)d_in[5];
    const float* bias  = (const float*)d_in[6];
    const float* gamma = (const float*)d_in[7];
    const float* beta  = (const float*)d_in[8];

    float *xrp, *kp, *vp, *aop, *wtq, *wtk, *wtv, *wtp, *wct, *cpart;
    cudaGetSymbolAddress((void**)&xrp,   g_xrp);
    cudaGetSymbolAddress((void**)&kp,    g_kp);
    cudaGetSymbolAddress((void**)&vp,    g_vp);
    cudaGetSymbolAddress((void**)&aop,   g_aop);
    cudaGetSymbolAddress((void**)&wtq,   g_wtq);
    cudaGetSymbolAddress((void**)&wtk,   g_wtk);
    cudaGetSymbolAddress((void**)&wtv,   g_wtv);
    cudaGetSymbolAddress((void**)&wtp,   g_wtp);
    cudaGetSymbolAddress((void**)&wct,   g_wct);
    cudaGetSymbolAddress((void**)&cpart, g_cpart);

    pack_w4_kernel<<<256, 256>>>(Wq, Wk, Wv, Wp, wtq, wtk, wtv, wtp);
    pack_wconv_kernel<<<1024, 256>>>(Wsr, wct);

    conv_part_kernel<<<dim3(MCONV / 32, 4), 256>>>(x, wct, cpart);             // SR conv
    ln_combine_kernel<<<MCONV, 128>>>(cpart, bias, gamma, beta, xrp);          // +bias+LN
    kv_proj_kernel<<<dim3(MCONV / 64, 2), 256>>>(xrp, wtk, wtv, kp, vp);       // K,V proj -> permuted
    attn_fused_kernel<<<dim3(NQ / QTILE, HEADS, BATCH), 256>>>(x, wtq, kp, vp, aop);
    gemm_frag_kernel<<<MQ / 64, 256>>>(aop, wtp, (float*)d_out);               // out proj
}

// round 14
// speedup vs baseline: 1.3829x; 1.3829x over previous
#include <cuda_runtime.h>
#include <math.h>

// ---------------------------------------------------------------------------
// Problem constants: B=4, N=16384 (H=W=128), C=128, HEADS=2, dh=64, SR=4
// ---------------------------------------------------------------------------
#define BATCH   4
#define NQ      16384
#define C_DIM   128
#define HEADS   2
#define DH      64
#define NKV     1024
#define QTILE   128
#define KCH     32
#define KCONV   2048
#define MCONV   (BATCH * NKV)     // 4096
#define MQ      (BATCH * NQ)      // 65536

// Scratch (allocation-free rule: __device__ globals)
__device__ float g_xrp  [MCONV * C_DIM];          // xr, fragment-permuted [kcg][m][16]
__device__ float g_kp   [BATCH * HEADS * 4 * NKV * 16];   // K frag-permuted [bh][kg_d][key][pos16]
__device__ float g_vp   [BATCH * HEADS * 64 * DH * 16];   // V^T frag-permuted [bh][kg_key][d][pos16]
__device__ float g_aop  [MQ * C_DIM];             // attn out, fragment-permuted
__device__ float g_cpart[4 * MCONV * C_DIM];      // conv split-K partials
// Pre-permuted tf32 weights: [kcg][n][pos16], k = kcg*16 + perm16(pos)
__device__ float g_wtq[C_DIM * C_DIM];
__device__ float g_wtk[C_DIM * C_DIM];
__device__ float g_wtv[C_DIM * C_DIM];
__device__ float g_wtp[C_DIM * C_DIM];
__device__ float g_wct[C_DIM * KCONV];

// ---------------------------------------------------------------------------
// tf32 helpers (fragment mappings validated R5-R13)
// ---------------------------------------------------------------------------
__device__ __forceinline__ unsigned f2tf(float x) {
    unsigned r;
    asm("cvt.rna.tf32.f32 %0, %1;" : "=r"(r) : "f"(x));
    return r;
}
__device__ __forceinline__ float f2tff(float x) {
    return __uint_as_float(f2tf(x));
}
__device__ __forceinline__ void mma_tf32(float& d0, float& d1, float& d2, float& d3,
                                         unsigned a0, unsigned a1, unsigned a2, unsigned a3,
                                         unsigned b0, unsigned b1) {
    asm volatile(
        "mma.sync.aligned.m16n8k8.row.col.f32.tf32.tf32.f32 "
        "{%0,%1,%2,%3},{%4,%5,%6,%7},{%8,%9},{%0,%1,%2,%3};"
        : "+f"(d0), "+f"(d1), "+f"(d2), "+f"(d3)
        : "r"(a0), "r"(a1), "r"(a2), "r"(a3), "r"(b0), "r"(b1));
}

// 4x4 transpose within a 16-group (involution): kk at pos (kk&3)*4 + (kk>>2).
__device__ __forceinline__ int perm16(int p) { return (p & 3) * 4 + (p >> 2); }

// Permuted scatter-store for activations into smem: chunk layout [kg][row][pos16].
__device__ __forceinline__ void sts_perm(float* s, int rows16, int row, int c4, float4 v) {
    float* base = s + ((c4 >> 2) * rows16 * 16) + row * 16 + (c4 & 3);
    base[0] = v.x; base[4] = v.y; base[8] = v.z; base[12] = v.w;
}

// ---------------------------------------------------------------------------
// Weight pack kernels
// ---------------------------------------------------------------------------
__global__ void pack_w4_kernel(const float* __restrict__ s0, const float* __restrict__ s1,
                               const float* __restrict__ s2, const float* __restrict__ s3,
                               float* __restrict__ d0, float* __restrict__ d1,
                               float* __restrict__ d2, float* __restrict__ d3) {
    int id = blockIdx.x * 256 + threadIdx.x;
    int mat = id >> 14, e = id & 16383;
    const float* s = (mat == 0) ? s0 : (mat == 1) ? s1 : (mat == 2) ? s2 : s3;
    float*       d = (mat == 0) ? d0 : (mat == 1) ? d1 : (mat == 2) ? d2 : d3;
    int pos = e & 15, n = (e >> 4) & 127, kcg = e >> 11;
    int k = kcg * 16 + perm16(pos);
    d[e] = f2tff(s[k * 128 + n]);
}

__global__ void pack_wconv_kernel(const float* __restrict__ src, float* __restrict__ dst) {
    int e = blockIdx.x * 256 + threadIdx.x;
    int pos = e & 15, n = (e >> 4) & 127, kcg = e >> 11;
    int k = kcg * 16 + perm16(pos);
    dst[e] = f2tff(src[(size_t)k * 128 + n]);
}

// ---------------------------------------------------------------------------
// Smem-free warp-autonomous GEMM core (R12-validated).
// ---------------------------------------------------------------------------
__device__ __forceinline__ void gemm_frag_compute(const float* __restrict__ Ap,
                                                  const float* __restrict__ Wp,
                                                  size_t M, size_t m,
                                                  int ng, int gid, int tig,
                                                  float oacc[8][4]) {
#pragma unroll
    for (int kcg = 0; kcg < 8; kcg++) {
        const float* ab = Ap + ((size_t)kcg * M + m) * 16 + (tig << 2);
        float4 alo = *(const float4*)ab;
        float4 ahi = *(const float4*)(ab + 128);
        unsigned a0 = __float_as_uint(alo.x), a1 = __float_as_uint(ahi.x);
        unsigned a2 = __float_as_uint(alo.y), a3 = __float_as_uint(ahi.y);
        unsigned c0 = __float_as_uint(alo.z), c1 = __float_as_uint(ahi.z);
        unsigned c2 = __float_as_uint(alo.w), c3 = __float_as_uint(ahi.w);
        const float* wb = Wp + ((size_t)kcg * 128 + ng * 64 + gid) * 16 + (tig << 2);
#pragma unroll
        for (int nt = 0; nt < 8; nt++) {
            float4 bv = *(const float4*)(wb + nt * 128);
            mma_tf32(oacc[nt][0], oacc[nt][1], oacc[nt][2], oacc[nt][3],
                     a0, a1, a2, a3, __float_as_uint(bv.x), __float_as_uint(bv.y));
            mma_tf32(oacc[nt][0], oacc[nt][1], oacc[nt][2], oacc[nt][3],
                     c0, c1, c2, c3, __float_as_uint(bv.z), __float_as_uint(bv.w));
        }
    }
}

__global__ __launch_bounds__(256)
void gemm_frag_kernel(const float* __restrict__ Ap, const float* __restrict__ Wp,
                      float* __restrict__ out) {
    int tid = threadIdx.x;
    int w = tid >> 5, lane = tid & 31;
    int gid = lane >> 2, tig = lane & 3;
    int mg = w & 3, ng = w >> 2;
    size_t m = ((size_t)blockIdx.x << 6) + mg * 16 + gid;
    float oacc[8][4];
#pragma unroll
    for (int i = 0; i < 8; i++)
#pragma unroll
        for (int j = 0; j < 4; j++) oacc[i][j] = 0.f;
    gemm_frag_compute(Ap, Wp, (size_t)MQ, m, ng, gid, tig, oacc);
    size_t r0 = m * 128, r1 = r0 + 8 * 128;
#pragma unroll
    for (int nt = 0; nt < 8; nt++) {
        int c = ng * 64 + nt * 8 + 2 * tig;
        *(float2*)&out[r0 + c] = make_float2(oacc[nt][0], oacc[nt][1]);
        *(float2*)&out[r1 + c] = make_float2(oacc[nt][2], oacc[nt][3]);
    }
}

// ---------------------------------------------------------------------------
// K/V projection with fragment-permuted epilogues (R13-validated).
// ---------------------------------------------------------------------------
__global__ __launch_bounds__(256)
void kv_proj_kernel(const float* __restrict__ Ap,
                    const float* __restrict__ Wpk, const float* __restrict__ Wpv,
                    float* __restrict__ kp, float* __restrict__ vp) {
    int tid = threadIdx.x;
    int w = tid >> 5, lane = tid & 31;
    int gid = lane >> 2, tig = lane & 3;
    int mg = w & 3, ng = w >> 2;        // ng == head
    int isV = blockIdx.y;
    size_t m = ((size_t)blockIdx.x << 6) + mg * 16 + gid;
    float oacc[8][4];
#pragma unroll
    for (int i = 0; i < 8; i++)
#pragma unroll
        for (int j = 0; j < 4; j++) oacc[i][j] = 0.f;
    gemm_frag_compute(Ap, isV ? Wpv : Wpk, (size_t)MCONV, m, ng, gid, tig, oacc);

    int b   = (int)(m >> 10);
    int key = (int)(m & 1023);
    int bh  = b * HEADS + ng;
    if (!isV) {
#pragma unroll
        for (int nt = 0; nt < 8; nt++) {
            int dl = nt * 8 + 2 * tig;
            int kg = dl >> 4;
            int p0 = perm16(dl & 15);
            float* b0 = kp + (((size_t)bh * 4 + kg) * NKV + key) * 16;
            float* b1 = b0 + 8 * 16;
            b0[p0]     = f2tff(oacc[nt][0]);
            b0[p0 + 4] = f2tff(oacc[nt][1]);
            b1[p0]     = f2tff(oacc[nt][2]);
            b1[p0 + 4] = f2tff(oacc[nt][3]);
        }
    } else {
        int kgk = key >> 4;
        int pa = perm16(gid), pb = perm16(gid + 8);
#pragma unroll
        for (int nt = 0; nt < 8; nt++) {
            int dl = nt * 8 + 2 * tig;
            float* bse = vp + (((size_t)bh * 64 + kgk) * DH + dl) * 16;
            bse[pa]      = f2tff(oacc[nt][0]);
            bse[16 + pa] = f2tff(oacc[nt][1]);
            bse[pb]      = f2tff(oacc[nt][2]);
            bse[16 + pb] = f2tff(oacc[nt][3]);
        }
    }
}

// ---------------------------------------------------------------------------
// Conv split-K x4 (R10-validated, unchanged).
// ---------------------------------------------------------------------------
__global__ __launch_bounds__(256)
void conv_part_kernel(const float* __restrict__ x, const float* __restrict__ Wp,
                      float* __restrict__ cpart) {
    __shared__ float sA[2][1024];
    int m0 = blockIdx.x << 5;
    int kz = blockIdx.y;
    int tid = threadIdx.x;
    int w = tid >> 5, lane = tid & 31;
    int gid = lane >> 2, tig = lane & 3;
    int rg = w & 1, cg = w >> 1;

    int lrow = tid >> 3, lc4 = tid & 7;
    int am = m0 + lrow;
    int ab = am >> 10, apos = am & 1023, aoh = apos >> 5, aow = apos & 31;
    const float* abase = x + ((size_t)((ab * 128 + (aoh << 2) + kz) * 128 + (aow << 2))) * 128;

    float oacc[4][4];
#pragma unroll
    for (int i = 0; i < 4; i++)
#pragma unroll
        for (int j = 0; j < 4; j++) oacc[i][j] = 0.f;

    float4 av = *(const float4*)(abase + (lc4 << 2));
    {
        float4 a = av;
        a.x = f2tff(a.x); a.y = f2tff(a.y); a.z = f2tff(a.z); a.w = f2tff(a.w);
        sts_perm(sA[0], 32, lrow, lc4, a);
    }
    __syncthreads();

#pragma unroll 1
    for (int cc = 0; cc < 16; cc++) {
        int cur = cc & 1;
        if (cc < 15) {
            int nc = cc + 1;
            int kw = nc >> 2, ci0 = (nc & 3) << 5;
            av = *(const float4*)(abase + (size_t)kw * 128 + ci0 + (lc4 << 2));
        }
        int kcg0 = (kz * 16 + cc) * 2;
#pragma unroll
        for (int kg = 0; kg < 2; kg++) {
            const float* pa = &sA[cur][kg * 512 + (rg * 16 + gid) * 16 + (tig << 2)];
            float4 alo = *(const float4*)pa;
            float4 ahi = *(const float4*)(pa + 128);
            unsigned a0 = __float_as_uint(alo.x), a1 = __float_as_uint(ahi.x);
            unsigned a2 = __float_as_uint(alo.y), a3 = __float_as_uint(ahi.y);
            unsigned c0 = __float_as_uint(alo.z), c1 = __float_as_uint(ahi.z);
            unsigned c2 = __float_as_uint(alo.w), c3 = __float_as_uint(ahi.w);
            const float* wb = Wp + ((size_t)(kcg0 + kg) * 128 + cg * 32 + gid) * 16 + (tig << 2);
#pragma unroll
            for (int nt = 0; nt < 4; nt++) {
                float4 bv = *(const float4*)(wb + nt * 128);
                mma_tf32(oacc[nt][0], oacc[nt][1], oacc[nt][2], oacc[nt][3],
                         a0, a1, a2, a3, __float_as_uint(bv.x), __float_as_uint(bv.y));
                mma_tf32(oacc[nt][0], oacc[nt][1], oacc[nt][2], oacc[nt][3],
                         c0, c1, c2, c3, __float_as_uint(bv.z), __float_as_uint(bv.w));
            }
        }
        if (cc < 15) {
            float4 a = av;
            a.x = f2tff(a.x); a.y = f2tff(a.y); a.z = f2tff(a.z); a.w = f2tff(a.w);
            sts_perm(sA[1 - cur], 32, lrow, lc4, a);
            __syncthreads();
        }
    }

    float* pb = cpart + (size_t)kz * MCONV * 128;
    size_t r0 = (size_t)(m0 + rg * 16 + gid) * 128;
    size_t r1 = r0 + 8 * 128;
#pragma unroll
    for (int nt = 0; nt < 4; nt++) {
        int c = cg * 32 + nt * 8 + 2 * tig;
        *(float2*)&pb[r0 + c] = make_float2(oacc[nt][0], oacc[nt][1]);
        *(float2*)&pb[r1 + c] = make_float2(oacc[nt][2], oacc[nt][3]);
    }
}

// ---------------------------------------------------------------------------
// LN combine -> permuted xr (R12-validated).
// ---------------------------------------------------------------------------
__global__ __launch_bounds__(128)
void ln_combine_kernel(const float* __restrict__ cpart, const float* __restrict__ bias,
                       const float* __restrict__ gamma, const float* __restrict__ beta,
                       float* __restrict__ xrp) {
    __shared__ float ss[4], ssq[4], sMR[2];
    int m = blockIdx.x, c = threadIdx.x;
    int wd = c >> 5, ln = c & 31;
    float v = bias[c];
#pragma unroll
    for (int z = 0; z < 4; z++)
        v += cpart[((size_t)z * MCONV + m) * 128 + c];
    float s = v, sq = v * v;
#pragma unroll
    for (int off = 16; off > 0; off >>= 1) {
        s  += __shfl_xor_sync(0xffffffffu, s, off);
        sq += __shfl_xor_sync(0xffffffffu, sq, off);
    }
    if (ln == 0) { ss[wd] = s; ssq[wd] = sq; }
    __syncthreads();
    if (c == 0) {
        float S = ss[0] + ss[1] + ss[2] + ss[3];
        float Q = ssq[0] + ssq[1] + ssq[2] + ssq[3];
        float mu = S * 0.0078125f;
        float var = Q * 0.0078125f - mu * mu;
        sMR[0] = mu; sMR[1] = rsqrtf(var + 1e-6f);
    }
    __syncthreads();
    float r = (v - sMR[0]) * sMR[1] * gamma[c] + beta[c];
    int kcg = c >> 4, pp = perm16(c & 15);
    xrp[((size_t)kcg * MCONV + m) * 16 + pp] = f2tff(r);
}

// ---------------------------------------------------------------------------
// Fused Qproj + flash attention. K/V staged in SMEM (amortized across warps,
// the R13 lesson) in fragment-permuted layout: staging = verbatim float4 copy,
// fragment reads = conflict-free LDS.128.
// ---------------------------------------------------------------------------
__global__ __launch_bounds__(256)
void attn_fused_kernel(const float* __restrict__ x, const float* __restrict__ Wqp,
                       const float* __restrict__ Kp, const float* __restrict__ Vp,
                       float* __restrict__ AOP) {
    __shared__ float smemU[9088];
    float* sKp = smemU;            // 2048: K chunk [kg_d=4][key32][16]
    float* sVp = smemU + 2048;     // 2048: V chunk [kgk=2][d64][16]
    float* sP  = smemU + 4480;     // 128*36 (warp-private rows)
    float* sSt = smemU;            // prologue staging: 2 x 4096
    float* sQ  = smemU;            // prologue Q park: 128*68

    int b  = blockIdx.z, h = blockIdx.y;
    int n0 = blockIdx.x * QTILE;
    int tid  = threadIdx.x;
    int w    = tid >> 5;
    int lane = tid & 31;
    int gid  = lane >> 2;
    int tig  = lane & 3;

    // ===== PROLOGUE: Q = x_tile @ Wq[:, h*64 .. h*64+63]  (R11-validated) =====
    {
        const float* A = x + ((size_t)(b * NQ + n0)) * C_DIM;
        int lrow = tid >> 3, lc4 = tid & 7;
        float qc[8][4];
#pragma unroll
        for (int i = 0; i < 8; i++)
#pragma unroll
            for (int j = 0; j < 4; j++) qc[i][j] = 0.f;

        float4 av[4];
#pragma unroll
        for (int i = 0; i < 4; i++)
            av[i] = *(const float4*)&A[(size_t)(lrow + (i << 5)) * 128 + (lc4 << 2)];
#pragma unroll
        for (int i = 0; i < 4; i++) {
            float4 a = av[i];
            a.x = f2tff(a.x); a.y = f2tff(a.y); a.z = f2tff(a.z); a.w = f2tff(a.w);
            sts_perm(sSt, 128, lrow + (i << 5), lc4, a);
        }
        __syncthreads();

#pragma unroll
        for (int kc = 0; kc < 4; kc++) {
            int cur = kc & 1;
            if (kc < 3) {
#pragma unroll
                for (int i = 0; i < 4; i++)
                    av[i] = *(const float4*)&A[(size_t)(lrow + (i << 5)) * 128 + ((kc + 1) << 5) + (lc4 << 2)];
            }
#pragma unroll
            for (int kg = 0; kg < 2; kg++) {
                const float* pa = &sSt[cur * 4096 + kg * 2048 + (w * 16 + gid) * 16 + (tig << 2)];
                float4 alo = *(const float4*)pa;
                float4 ahi = *(const float4*)(pa + 128);
                unsigned a0 = __float_as_uint(alo.x), a1 = __float_as_uint(ahi.x);
                unsigned a2 = __float_as_uint(alo.y), a3 = __float_as_uint(ahi.y);
                unsigned c0 = __float_as_uint(alo.z), c1 = __float_as_uint(ahi.z);
                unsigned c2 = __float_as_uint(alo.w), c3 = __float_as_uint(ahi.w);
                const float* wb = Wqp + ((size_t)(kc * 2 + kg) * 128 + h * 64 + gid) * 16 + (tig << 2);
#pragma unroll
                for (int nt = 0; nt < 8; nt++) {
                    float4 bv = *(const float4*)(wb + nt * 128);
                    mma_tf32(qc[nt][0], qc[nt][1], qc[nt][2], qc[nt][3],
                             a0, a1, a2, a3, __float_as_uint(bv.x), __float_as_uint(bv.y));
                    mma_tf32(qc[nt][0], qc[nt][1], qc[nt][2], qc[nt][3],
                             c0, c1, c2, c3, __float_as_uint(bv.z), __float_as_uint(bv.w));
                }
            }
            if (kc < 3) {
#pragma unroll
                for (int i = 0; i < 4; i++) {
                    float4 a = av[i];
                    a.x = f2tff(a.x); a.y = f2tff(a.y); a.z = f2tff(a.z); a.w = f2tff(a.w);
                    sts_perm(sSt + (1 - cur) * 4096, 128, lrow + (i << 5), lc4, a);
                }
                __syncthreads();
            }
        }
        __syncthreads();

        int r0 = w * 16 + gid, r1 = r0 + 8;
#pragma unroll
        for (int nt = 0; nt < 8; nt++) {
            int c = nt * 8 + 2 * tig;
            float2 e0, e1;
            e0.x = f2tff(qc[nt][0] * 0.125f); e0.y = f2tff(qc[nt][1] * 0.125f);
            e1.x = f2tff(qc[nt][2] * 0.125f); e1.y = f2tff(qc[nt][3] * 0.125f);
            *(float2*)&sQ[r0 * 68 + c] = e0;
            *(float2*)&sQ[r1 * 68 + c] = e1;
        }
        __syncthreads();
    }

    unsigned qa[8][4];
    {
        int r0 = w * 16 + gid, r1 = r0 + 8;
#pragma unroll
        for (int ks = 0; ks < 8; ks++) {
            int c = ks * 8 + tig;
            qa[ks][0] = __float_as_uint(sQ[r0 * 68 + c]);
            qa[ks][1] = __float_as_uint(sQ[r1 * 68 + c]);
            qa[ks][2] = __float_as_uint(sQ[r0 * 68 + c + 4]);
            qa[ks][3] = __float_as_uint(sQ[r1 * 68 + c + 4]);
        }
    }
    __syncthreads();   // all warps done reading sQ before mainloop smem writes

    // ===== MAINLOOP: permuted K/V chunks staged in smem, LDS.128 frags =====
    int bh = b * HEADS + h;
    const float* KpB = Kp + (size_t)bh * 4 * NKV * 16;
    const float* VpB = Vp + (size_t)bh * 64 * DH * 16;
    int remk = tid & 127;          // K loader: 512 floats per kg group
    int kgA  = tid >> 7;           // 0 or 1 (this thread covers kgA and kgA+2)

    float oacc[8][4];
#pragma unroll
    for (int i = 0; i < 8; i++)
#pragma unroll
        for (int j = 0; j < 4; j++) oacc[i][j] = 0.f;
    float m0r = -1e30f, m1r = -1e30f, l0 = 0.f, l1 = 0.f;
    int r0off = (w * 16 + gid) * 36;
    int r1off = r0off + 8 * 36;

    // prefetch chunk 0 (verbatim tf32 data, no conversion)
    float4 pf0 = *(const float4*)(KpB + ((size_t)kgA       * NKV) * 16 + remk * 4);
    float4 pf1 = *(const float4*)(KpB + ((size_t)(kgA + 2) * NKV) * 16 + remk * 4);
    float4 pf2 = *(const float4*)(VpB + (size_t)tid * 4);
    float4 pf3 = *(const float4*)(VpB + 1024 + (size_t)tid * 4);

#pragma unroll 1
    for (int kc = 0; kc < NKV / KCH; kc++) {
        __syncthreads();   // prior chunk fully consumed
        *(float4*)&sKp[kgA * 512 + remk * 4]       = pf0;
        *(float4*)&sKp[(kgA + 2) * 512 + remk * 4] = pf1;
        *(float4*)&sVp[tid * 4]                    = pf2;
        *(float4*)&sVp[1024 + tid * 4]             = pf3;
        __syncthreads();
        if (kc < NKV / KCH - 1) {   // prefetch next (overlaps compute)
            int nk = kc + 1;
            pf0 = *(const float4*)(KpB + ((size_t)kgA * NKV + nk * 32) * 16 + remk * 4);
            pf1 = *(const float4*)(KpB + ((size_t)(kgA + 2) * NKV + nk * 32) * 16 + remk * 4);
            pf2 = *(const float4*)(VpB + (size_t)(nk * 2) * 1024 + tid * 4);
            pf3 = *(const float4*)(VpB + (size_t)(nk * 2 + 1) * 1024 + tid * 4);
        }

        // ---- QK: S[16x32]; K frags = conflict-free LDS.128 ----
        float sacc[4][4];
#pragma unroll
        for (int i = 0; i < 4; i++)
#pragma unroll
            for (int j = 0; j < 4; j++) sacc[i][j] = 0.f;
#pragma unroll
        for (int kg = 0; kg < 4; kg++) {
            float4 bv[4];
#pragma unroll
            for (int nt = 0; nt < 4; nt++)
                bv[nt] = *(const float4*)&sKp[kg * 512 + (nt * 8 + gid) * 16 + (tig << 2)];
#pragma unroll
            for (int nt = 0; nt < 4; nt++) {
                mma_tf32(sacc[nt][0], sacc[nt][1], sacc[nt][2], sacc[nt][3],
                         qa[2 * kg][0], qa[2 * kg][1], qa[2 * kg][2], qa[2 * kg][3],
                         __float_as_uint(bv[nt].x), __float_as_uint(bv[nt].y));
                mma_tf32(sacc[nt][0], sacc[nt][1], sacc[nt][2], sacc[nt][3],
                         qa[2 * kg + 1][0], qa[2 * kg + 1][1], qa[2 * kg + 1][2], qa[2 * kg + 1][3],
                         __float_as_uint(bv[nt].z), __float_as_uint(bv[nt].w));
            }
        }

        // ---- online softmax (validated) ----
        float cm0 = -1e30f, cm1 = -1e30f;
#pragma unroll
        for (int nt = 0; nt < 4; nt++) {
            cm0 = fmaxf(cm0, fmaxf(sacc[nt][0], sacc[nt][1]));
            cm1 = fmaxf(cm1, fmaxf(sacc[nt][2], sacc[nt][3]));
        }
        cm0 = fmaxf(cm0, __shfl_xor_sync(0xffffffffu, cm0, 1));
        cm0 = fmaxf(cm0, __shfl_xor_sync(0xffffffffu, cm0, 2));
        cm1 = fmaxf(cm1, __shfl_xor_sync(0xffffffffu, cm1, 1));
        cm1 = fmaxf(cm1, __shfl_xor_sync(0xffffffffu, cm1, 2));
        float mn0 = fmaxf(m0r, cm0), mn1 = fmaxf(m1r, cm1);
        float al0 = __expf(m0r - mn0), al1 = __expf(m1r - mn1);
        float ps0 = 0.f, ps1 = 0.f;
#pragma unroll
        for (int nt = 0; nt < 4; nt++) {
            float p0 = __expf(sacc[nt][0] - mn0);
            float p1 = __expf(sacc[nt][1] - mn0);
            float p2 = __expf(sacc[nt][2] - mn1);
            float p3 = __expf(sacc[nt][3] - mn1);
            ps0 += p0 + p1;
            ps1 += p2 + p3;
            int co = nt * 8 + 2 * tig;
            float2 e0, e1;
            e0.x = f2tff(p0); e0.y = f2tff(p1);
            e1.x = f2tff(p2); e1.y = f2tff(p3);
            *(float2*)&sP[r0off + co] = e0;
            *(float2*)&sP[r1off + co] = e1;
        }
        ps0 += __shfl_xor_sync(0xffffffffu, ps0, 1);
        ps0 += __shfl_xor_sync(0xffffffffu, ps0, 2);
        ps1 += __shfl_xor_sync(0xffffffffu, ps1, 1);
        ps1 += __shfl_xor_sync(0xffffffffu, ps1, 2);
        l0 = l0 * al0 + ps0;  m0r = mn0;
        l1 = l1 * al1 + ps1;  m1r = mn1;
#pragma unroll
        for (int nt = 0; nt < 8; nt++) {
            oacc[nt][0] *= al0; oacc[nt][1] *= al0;
            oacc[nt][2] *= al1; oacc[nt][3] *= al1;
        }
        __syncwarp();

        // ---- PV: O += P * V; V frags = conflict-free LDS.128 ----
#pragma unroll
        for (int kgk = 0; kgk < 2; kgk++) {
            int ks0 = 2 * kgk, ks1 = ks0 + 1;
            unsigned a0 = __float_as_uint(sP[r0off + ks0 * 8 + tig]);
            unsigned a1 = __float_as_uint(sP[r1off + ks0 * 8 + tig]);
            unsigned a2 = __float_as_uint(sP[r0off + ks0 * 8 + tig + 4]);
            unsigned a3 = __float_as_uint(sP[r1off + ks0 * 8 + tig + 4]);
            unsigned d0 = __float_as_uint(sP[r0off + ks1 * 8 + tig]);
            unsigned d1 = __float_as_uint(sP[r1off + ks1 * 8 + tig]);
            unsigned d2 = __float_as_uint(sP[r0off + ks1 * 8 + tig + 4]);
            unsigned d3 = __float_as_uint(sP[r1off + ks1 * 8 + tig + 4]);
#pragma unroll
            for (int nt = 0; nt < 8; nt++) {
                float4 bv = *(const float4*)&sVp[kgk * 1024 + (nt * 8 + gid) * 16 + (tig << 2)];
                mma_tf32(oacc[nt][0], oacc[nt][1], oacc[nt][2], oacc[nt][3],
                         a0, a1, a2, a3, __float_as_uint(bv.x), __float_as_uint(bv.y));
                mma_tf32(oacc[nt][0], oacc[nt][1], oacc[nt][2], oacc[nt][3],
                         d0, d1, d2, d3, __float_as_uint(bv.z), __float_as_uint(bv.w));
            }
        }
    }

    // ===== EPILOGUE: permuted fragment-ready ao (R12-validated) =====
    float inv0 = 1.f / l0, inv1 = 1.f / l1;
    size_t mrow = (size_t)(b * NQ + n0 + w * 16 + gid);
#pragma unroll
    for (int nt = 0; nt < 8; nt++) {
        int c = h * 64 + nt * 8 + 2 * tig;
        int kcg = c >> 4;
        int pp = perm16(c & 15);
        float* base0 = AOP + ((size_t)kcg * MQ + mrow) * 16;
        float* base1 = base0 + 128;
        base0[pp]     = f2tff(oacc[nt][0] * inv0);
        base0[pp + 4] = f2tff(oacc[nt][1] * inv0);
        base1[pp]     = f2tff(oacc[nt][2] * inv1);
        base1[pp + 4] = f2tff(oacc[nt][3] * inv1);
    }
}

// ---------------------------------------------------------------------------
// Launch. Inputs: x, Wq, Wk, Wv, Wproj, sr_kernel, sr_bias, gamma, beta.
// ---------------------------------------------------------------------------
extern "C" void kernel_launch(void* const* d_in, const int* in_sizes, int n_in,
                              void* d_out, int out_size) {
    const float* x     = (const float*)d_in[0];
    const float* Wq    = (const float*)d_in[1];
    const float* Wk    = (const float*)d_in[2];
    const float* Wv    = (const float*)d_in[3];
    const float* Wp    = (const float*)d_in[4];
    const float* Wsr   = (const float*)d_in[5];
    const float* bias  = (const float*)d_in[6];
    const float* gamma = (const float*)d_in[7];
    const float* beta  = (const float*)d_in[8];

    float *xrp, *kp, *vp, *aop, *wtq, *wtk, *wtv, *wtp, *wct, *cpart;
    cudaGetSymbolAddress((void**)&xrp,   g_xrp);
    cudaGetSymbolAddress((void**)&kp,    g_kp);
    cudaGetSymbolAddress((void**)&vp,    g_vp);
    cudaGetSymbolAddress((void**)&aop,   g_aop);
    cudaGetSymbolAddress((void**)&wtq,   g_wtq);
    cudaGetSymbolAddress((void**)&wtk,   g_wtk);
    cudaGetSymbolAddress((void**)&wtv,   g_wtv);
    cudaGetSymbolAddress((void**)&wtp,   g_wtp);
    cudaGetSymbolAddress((void**)&wct,   g_wct);
    cudaGetSymbolAddress((void**)&cpart, g_cpart);

    pack_w4_kernel<<<256, 256>>>(Wq, Wk, Wv, Wp, wtq, wtk, wtv, wtp);
    pack_wconv_kernel<<<1024, 256>>>(Wsr, wct);

    conv_part_kernel<<<dim3(MCONV / 32, 4), 256>>>(x, wct, cpart);             // SR conv
    ln_combine_kernel<<<MCONV, 128>>>(cpart, bias, gamma, beta, xrp);          // +bias+LN
    kv_proj_kernel<<<dim3(MCONV / 64, 2), 256>>>(xrp, wtk, wtv, kp, vp);       // K,V proj -> permuted
    attn_fused_kernel<<<dim3(NQ / QTILE, HEADS, BATCH), 256>>>(x, wtq, kp, vp, aop);
    gemm_frag_kernel<<<MQ / 64, 256>>>(aop, wtp, (float*)d_out);               // out proj
}